// round 1
// baseline (speedup 1.0000x reference)
#include <cuda_runtime.h>
#include <cuda_bf16.h>
#include <stdint.h>

// Problem constants (from reference): B=4, N=65536, NV=1, E=128, NH=7
#define B_  4
#define N_  65536
#define NH_ 7
#define E_  128

// x_nh elements = B*N*NH*E = 234,881,024 ; mask elements = B*N*NH = 1,835,008

// One warp per output row (b, n, h). 32 lanes x float4 = 128 floats = E.
// Streaming stores (.cs) keep the 939MB output from evicting x (128MB) in L2.
__global__ void __launch_bounds__(256) gather_nh_kernel(
    const float4* __restrict__ x,        // [B, N, E/4] as float4
    const int*    __restrict__ adjc,     // [N, NH]
    const int*    __restrict__ lidx,     // [B, N]
    const int*    __restrict__ bsi,      // [B]
    const int*    __restrict__ slvl,     // scalar
    float4*       __restrict__ out)      // [B, N, NH, E/4]
{
    const int warp = (blockIdx.x * blockDim.x + threadIdx.x) >> 5;
    const int lane = threadIdx.x & 31;
    const int total = B_ * N_ * NH_;
    if (warp >= total) return;

    const int b   = warp / (N_ * NH_);
    const int rem = warp - b * (N_ * NH_);
    const int n   = rem / NH_;
    const int h   = rem - n * NH_;

    const int li  = __ldg(&lidx[b * N_ + n]);
    const int off = __ldg(&bsi[b]) << (2 * __ldg(slvl));   // bsi * 4^sampled_level
    const int gi  = __ldg(&adjc[li * NH_ + h]) - off;

    const float4* src = x + ((size_t)b * N_ + (size_t)gi) * (E_ / 4);
    float4 v = __ldg(&src[lane]);
    __stcs(&out[(size_t)warp * (E_ / 4) + lane], v);
}

// Mask: out_mask[b,n,h] = adjc_mask_invalid[local_indices[b,n], h] ? 1 : 0
__global__ void __launch_bounds__(256) mask_nh_kernel(
    const unsigned char* __restrict__ mask_inv,  // [N, NH] bool bytes
    const int*           __restrict__ lidx,      // [B, N]
    float*               __restrict__ out)       // [B, N, NH]
{
    const int i = blockIdx.x * blockDim.x + threadIdx.x;
    const int total = B_ * N_ * NH_;
    if (i >= total) return;

    const int b   = i / (N_ * NH_);
    const int rem = i - b * (N_ * NH_);
    const int n   = rem / NH_;
    const int h   = rem - n * NH_;

    const int li = __ldg(&lidx[b * N_ + n]);
    __stcs(&out[i], __ldg(&mask_inv[li * NH_ + h]) ? 1.0f : 0.0f);
}

extern "C" void kernel_launch(void* const* d_in, const int* in_sizes, int n_in,
                              void* d_out, int out_size) {
    const float4*        x        = (const float4*)d_in[0];
    const int*           adjc     = (const int*)d_in[1];
    const unsigned char* mask_inv = (const unsigned char*)d_in[2];
    const int*           lidx     = (const int*)d_in[3];
    const int*           bsi      = (const int*)d_in[4];
    const int*           slvl     = (const int*)d_in[5];
    float*               out      = (float*)d_out;

    const long long xnh_elems  = (long long)B_ * N_ * NH_ * E_;   // 234,881,024
    const long long mask_elems = (long long)B_ * N_ * NH_;        // 1,835,008

    const int total_rows = B_ * N_ * NH_;
    const int warps_per_block = 256 / 32;
    const int gblocks = (total_rows + warps_per_block - 1) / warps_per_block;
    gather_nh_kernel<<<gblocks, 256>>>(x, adjc, lidx, bsi, slvl, (float4*)out);

    if ((long long)out_size >= xnh_elems + mask_elems) {
        const int mblocks = (int)((mask_elems + 255) / 256);
        mask_nh_kernel<<<mblocks, 256>>>(mask_inv, lidx, out + xnh_elems);
    }
}

// round 3
// speedup vs baseline: 1.7233x; 1.7233x over previous
#include <cuda_runtime.h>
#include <cuda_bf16.h>
#include <stdint.h>

// Problem constants (from reference): B=4, N=65536, NV=1, E=128, NH=7
#define B_  4
#define N_  65536
#define NH_ 7
#define E_  128
#define EV4 (E_ / 4)   // 32 float4 per row

// x_nh elements = B*N*NH*E = 234,881,024 ; mask elements = B*N*NH = 1,835,008

// One warp per (b, n): loads local index once, lanes 0..6 fetch the 7 adjc
// entries + mask bytes in parallel, then 7 independent 512B row gathers with
// full MLP. Streaming stores keep the 939MB output from evicting x in L2
// (x reuse factor ~7 across the gather).
__global__ void __launch_bounds__(256) gather_nh_fused_kernel(
    const float4*        __restrict__ x,        // [B, N, EV4]
    const int*           __restrict__ adjc,     // [N, NH]
    const unsigned char* __restrict__ mask_inv, // [N, NH]
    const int*           __restrict__ lidx,     // [B, N]
    const int*           __restrict__ bsi,      // [B]
    const int*           __restrict__ slvl,     // scalar
    float4*              __restrict__ out,      // [B, N, NH, EV4]
    float*               __restrict__ out_mask, // [B, N, NH]
    int                  write_mask)
{
    const int wg   = (blockIdx.x * blockDim.x + threadIdx.x) >> 5;  // (b,n) id
    const int lane = threadIdx.x & 31;
    if (wg >= B_ * N_) return;

    const int b = wg >> 16;        // N_ = 65536
    const int n = wg & (N_ - 1);

    const int li  = __ldg(&lidx[b * N_ + n]);
    const int off = __ldg(&bsi[b]) << (2 * __ldg(slvl));  // bsi * 4^sampled_level

    // Lanes 0..6 fetch the 7 neighbor ids (coalesced 28B) and mask bytes.
    int gi = 0;
    if (lane < NH_) {
        gi = __ldg(&adjc[li * NH_ + lane]) - off;
        if (write_mask) {
            out_mask[(size_t)wg * NH_ + lane] =
                __ldg(&mask_inv[li * NH_ + lane]) ? 1.0f : 0.0f;
        }
    }

    const float4* xb = x + (size_t)b * N_ * EV4;
    float4* ob = out + (size_t)wg * NH_ * EV4;

    // Resolve all 7 source addresses first (shfl lat=26 would otherwise space
    // out the load issues), then front-batch 7 independent LDG.128s, then store.
    const float4* src[NH_];
    #pragma unroll
    for (int h = 0; h < NH_; h++) {
        const int g = __shfl_sync(0xffffffffu, gi, h);
        src[h] = &xb[(size_t)g * EV4 + lane];
    }

    float4 v[NH_];
    #pragma unroll
    for (int h = 0; h < NH_; h++) v[h] = __ldg(src[h]);

    #pragma unroll
    for (int h = 0; h < NH_; h++) __stcs(&ob[h * EV4 + lane], v[h]);
}

extern "C" void kernel_launch(void* const* d_in, const int* in_sizes, int n_in,
                              void* d_out, int out_size) {
    const float4*        x        = (const float4*)d_in[0];
    const int*           adjc     = (const int*)d_in[1];
    const unsigned char* mask_inv = (const unsigned char*)d_in[2];
    const int*           lidx     = (const int*)d_in[3];
    const int*           bsi      = (const int*)d_in[4];
    const int*           slvl     = (const int*)d_in[5];
    float*               out      = (float*)d_out;

    const long long xnh_elems  = (long long)B_ * N_ * NH_ * E_;   // 234,881,024
    const long long mask_elems = (long long)B_ * N_ * NH_;        // 1,835,008
    const int write_mask = ((long long)out_size >= xnh_elems + mask_elems) ? 1 : 0;

    const int total_warps = B_ * N_;                 // 262,144
    const int warps_per_block = 256 / 32;
    const int blocks = (total_warps + warps_per_block - 1) / warps_per_block;

    gather_nh_fused_kernel<<<blocks, 256>>>(
        x, adjc, mask_inv, lidx, bsi, slvl,
        (float4*)out, out + xnh_elems, write_mask);
}